// round 1
// baseline (speedup 1.0000x reference)
#include <cuda_runtime.h>
#include <cuda_bf16.h>
#include <math.h>
#include <stdint.h>

#define NROWS 4096
#define HALF_N 2048
#define DD 512
#define INV_TAU 5.0f

#define BK 32
#define SSTR 40            // padded bf16 row stride (80 bytes) -> conflict-free ldmatrix
#define STAGE_BYTES (128 * SSTR * 2)
#define KT (DD / BK)       // 16 k-stages

// ---- device-global scratch (no allocations allowed) ----
__device__ __align__(16) __nv_bfloat16 g_zn_bf[NROWS * DD];
__device__ __align__(16) float         g_zn_f [NROWS * DD];
__device__ float g_row_sum[NROWS];
__device__ float g_loss_acc;

// ============================================================
// K1: normalize rows of concat(z1,z2); zero accumulators
// ============================================================
__global__ void k_normalize(const float* __restrict__ z1, const float* __restrict__ z2) {
    int row = blockIdx.x;
    const float* src = (row < HALF_N) ? (z1 + (size_t)row * DD)
                                      : (z2 + (size_t)(row - HALF_N) * DD);
    int t = threadIdx.x;                       // 128 threads, 4 floats each
    float4 v = ((const float4*)src)[t];
    float ss = v.x * v.x + v.y * v.y + v.z * v.z + v.w * v.w;
    #pragma unroll
    for (int o = 16; o; o >>= 1) ss += __shfl_xor_sync(0xffffffffu, ss, o);

    __shared__ float warp_ss[4];
    __shared__ float s_inv;
    if ((t & 31) == 0) warp_ss[t >> 5] = ss;
    __syncthreads();
    if (t == 0) {
        float tot = warp_ss[0] + warp_ss[1] + warp_ss[2] + warp_ss[3];
        float nrm = fmaxf(sqrtf(tot), 1e-8f);
        s_inv = 1.0f / nrm;
        g_row_sum[row] = 0.0f;
        if (row == 0) g_loss_acc = 0.0f;
    }
    __syncthreads();
    float inv = s_inv;
    float4 o;
    o.x = v.x * inv; o.y = v.y * inv; o.z = v.z * inv; o.w = v.w * inv;
    ((float4*)(g_zn_f + (size_t)row * DD))[t] = o;

    __nv_bfloat162 b0 = __float22bfloat162_rn(make_float2(o.x, o.y));
    __nv_bfloat162 b1 = __float22bfloat162_rn(make_float2(o.z, o.w));
    uint2 pk;
    pk.x = *(uint32_t*)&b0; pk.y = *(uint32_t*)&b1;
    ((uint2*)(g_zn_bf + (size_t)row * DD))[t] = pk;
}

// ============================================================
// K2: symmetric bf16 GEMM with fused exp-sum epilogue
// ============================================================
__device__ __forceinline__ void cp_async16(uint32_t saddr, const void* gptr) {
    asm volatile("cp.async.cg.shared.global [%0], [%1], 16;\n" :: "r"(saddr), "l"(gptr));
}
__device__ __forceinline__ void ldm_x4(uint32_t& r0, uint32_t& r1, uint32_t& r2, uint32_t& r3,
                                       uint32_t addr) {
    asm volatile("ldmatrix.sync.aligned.m8n8.x4.shared.b16 {%0,%1,%2,%3}, [%4];\n"
                 : "=r"(r0), "=r"(r1), "=r"(r2), "=r"(r3) : "r"(addr));
}
__device__ __forceinline__ void ldm_x2(uint32_t& r0, uint32_t& r1, uint32_t addr) {
    asm volatile("ldmatrix.sync.aligned.m8n8.x2.shared.b16 {%0,%1}, [%2];\n"
                 : "=r"(r0), "=r"(r1) : "r"(addr));
}
__device__ __forceinline__ void mma16816(float* c, uint32_t a0, uint32_t a1, uint32_t a2,
                                         uint32_t a3, uint32_t b0, uint32_t b1) {
    asm volatile("mma.sync.aligned.m16n8k16.row.col.f32.bf16.bf16.f32 "
                 "{%0,%1,%2,%3}, {%4,%5,%6,%7}, {%8,%9}, {%0,%1,%2,%3};\n"
                 : "+f"(c[0]), "+f"(c[1]), "+f"(c[2]), "+f"(c[3])
                 : "r"(a0), "r"(a1), "r"(a2), "r"(a3), "r"(b0), "r"(b1));
}

__global__ __launch_bounds__(256) void k_simgemm() {
    __shared__ __nv_bfloat16 sA[2][128 * SSTR];
    __shared__ __nv_bfloat16 sB[2][128 * SSTR];

    // linear block id -> (bm, bn), bm <= bn  (528 pairs of 32x32 tile grid)
    int idx = blockIdx.x;
    int bm = 0, rl = 32;
    while (idx >= rl) { idx -= rl; bm++; rl--; }
    int bn = bm + idx;
    bool diag = (bm == bn);

    int tid = threadIdx.x;
    int lane = tid & 31, warp = tid >> 5;
    int wm = warp >> 2, wn = warp & 3;        // warp tile: 64(m) x 32(n)

    uint32_t sA_u = (uint32_t)__cvta_generic_to_shared(&sA[0][0]);
    uint32_t sB_u = (uint32_t)__cvta_generic_to_shared(&sB[0][0]);

    // ---- gmem->smem loader lanes ----
    int ldr0 = tid >> 2, ldc0 = (tid & 3) * 8;   // rows 0..63
    int ldr1 = ldr0 + 64;                        // rows 64..127
    const __nv_bfloat16* gA0 = g_zn_bf + (size_t)(bm * 128 + ldr0) * DD + ldc0;
    const __nv_bfloat16* gA1 = g_zn_bf + (size_t)(bm * 128 + ldr1) * DD + ldc0;
    const __nv_bfloat16* gB0 = g_zn_bf + (size_t)(bn * 128 + ldr0) * DD + ldc0;
    const __nv_bfloat16* gB1 = g_zn_bf + (size_t)(bn * 128 + ldr1) * DD + ldc0;
    uint32_t sAd0 = sA_u + (uint32_t)(ldr0 * SSTR + ldc0) * 2;
    uint32_t sAd1 = sA_u + (uint32_t)(ldr1 * SSTR + ldc0) * 2;
    uint32_t sBd0 = sB_u + (uint32_t)(ldr0 * SSTR + ldc0) * 2;
    uint32_t sBd1 = sB_u + (uint32_t)(ldr1 * SSTR + ldc0) * 2;

#define PREFETCH(s, kt_) do {                                   \
        uint32_t so_ = (uint32_t)(s) * STAGE_BYTES;             \
        int ko_ = (kt_) * BK;                                   \
        cp_async16(sAd0 + so_, gA0 + ko_);                      \
        cp_async16(sAd1 + so_, gA1 + ko_);                      \
        cp_async16(sBd0 + so_, gB0 + ko_);                      \
        cp_async16(sBd1 + so_, gB1 + ko_);                      \
        asm volatile("cp.async.commit_group;\n");               \
    } while (0)

    // ---- ldmatrix per-thread base offsets ----
    uint32_t aOff = (uint32_t)(((lane & 15) + wm * 64) * SSTR + (lane >> 4) * 8) * 2;
    uint32_t bOff = (uint32_t)(((lane & 7) + wn * 32) * SSTR + ((lane >> 3) & 1) * 8) * 2;

    float acc[4][4][4];
    #pragma unroll
    for (int i = 0; i < 4; i++)
        #pragma unroll
        for (int j = 0; j < 4; j++)
            #pragma unroll
            for (int k = 0; k < 4; k++) acc[i][j][k] = 0.0f;

    PREFETCH(0, 0);

    for (int kt = 0; kt < KT; kt++) {
        asm volatile("cp.async.wait_group 0;\n");
        __syncthreads();
        int s = kt & 1;
        if (kt + 1 < KT) PREFETCH((kt + 1) & 1, kt + 1);

        uint32_t aBase = sA_u + (uint32_t)s * STAGE_BYTES + aOff;
        uint32_t bBase = sB_u + (uint32_t)s * STAGE_BYTES + bOff;
        #pragma unroll
        for (int k16 = 0; k16 < 2; k16++) {
            uint32_t a[4][4], b[4][2];
            #pragma unroll
            for (int mt = 0; mt < 4; mt++)
                ldm_x4(a[mt][0], a[mt][1], a[mt][2], a[mt][3],
                       aBase + (uint32_t)mt * (16 * SSTR * 2) + (uint32_t)k16 * 32);
            #pragma unroll
            for (int nt = 0; nt < 4; nt++)
                ldm_x2(b[nt][0], b[nt][1],
                       bBase + (uint32_t)nt * (8 * SSTR * 2) + (uint32_t)k16 * 32);
            #pragma unroll
            for (int mt = 0; mt < 4; mt++)
                #pragma unroll
                for (int nt = 0; nt < 4; nt++)
                    mma16816(acc[mt][nt], a[mt][0], a[mt][1], a[mt][2], a[mt][3],
                             b[nt][0], b[nt][1]);
        }
        __syncthreads();
    }

    // ---- epilogue: exp + per-row / per-col partial sums ----
    float rowPart[4][2], colPart[4][2];
    #pragma unroll
    for (int i = 0; i < 4; i++) {
        rowPart[i][0] = rowPart[i][1] = 0.0f;
        colPart[i][0] = colPart[i][1] = 0.0f;
    }
    #pragma unroll
    for (int mt = 0; mt < 4; mt++)
        #pragma unroll
        for (int nt = 0; nt < 4; nt++)
            #pragma unroll
            for (int j = 0; j < 4; j++) {
                float e = __expf(acc[mt][nt][j] * INV_TAU);
                if (diag) {
                    int r = wm * 64 + mt * 16 + (lane >> 2) + (j >> 1) * 8;
                    int c = wn * 32 + nt * 8 + (lane & 3) * 2 + (j & 1);
                    if (r == c) e = 0.0f;
                }
                rowPart[mt][j >> 1] += e;
                colPart[nt][j & 1] += e;
            }

    // rows: lanes sharing lane/4 hold the same row -> reduce over lane%4
    #pragma unroll
    for (int mt = 0; mt < 4; mt++)
        #pragma unroll
        for (int h = 0; h < 2; h++) {
            float v = rowPart[mt][h];
            v += __shfl_xor_sync(0xffffffffu, v, 1);
            v += __shfl_xor_sync(0xffffffffu, v, 2);
            if ((lane & 3) == 0)
                atomicAdd(&g_row_sum[bm * 128 + wm * 64 + mt * 16 + (lane >> 2) + h * 8], v);
        }
    // cols (symmetric contribution): lanes sharing lane%4 hold same col
    if (!diag) {
        #pragma unroll
        for (int nt = 0; nt < 4; nt++)
            #pragma unroll
            for (int p = 0; p < 2; p++) {
                float v = colPart[nt][p];
                v += __shfl_xor_sync(0xffffffffu, v, 4);
                v += __shfl_xor_sync(0xffffffffu, v, 8);
                v += __shfl_xor_sync(0xffffffffu, v, 16);
                if (lane < 4)
                    atomicAdd(&g_row_sum[bn * 128 + wn * 32 + nt * 8 + (lane & 3) * 2 + p], v);
            }
    }
#undef PREFETCH
}

// ============================================================
// K3: per-row loss term = log(row_sum) - pos_dot/tau, accumulate
// ============================================================
__global__ void k_rowterm() {
    int warp = threadIdx.x >> 5;
    int lane = threadIdx.x & 31;
    int row = blockIdx.x * 4 + warp;
    int pair = (row < HALF_N) ? row + HALF_N : row - HALF_N;
    const float4* a = (const float4*)(g_zn_f + (size_t)row * DD);
    const float4* b = (const float4*)(g_zn_f + (size_t)pair * DD);
    float dot = 0.0f;
    #pragma unroll
    for (int i = 0; i < 4; i++) {
        float4 va = a[lane + i * 32];
        float4 vb = b[lane + i * 32];
        dot += va.x * vb.x + va.y * vb.y + va.z * vb.z + va.w * vb.w;
    }
    #pragma unroll
    for (int o = 16; o; o >>= 1) dot += __shfl_xor_sync(0xffffffffu, dot, o);
    if (lane == 0) {
        float term = logf(g_row_sum[row]) - dot * INV_TAU;
        atomicAdd(&g_loss_acc, term);
    }
}

// ============================================================
// K4: finalize
// ============================================================
__global__ void k_final(float* out) { out[0] = g_loss_acc * (1.0f / NROWS); }

extern "C" void kernel_launch(void* const* d_in, const int* in_sizes, int n_in,
                              void* d_out, int out_size) {
    const float* z1 = (const float*)d_in[0];
    const float* z2 = (const float*)d_in[1];
    float* out = (float*)d_out;
    k_normalize<<<NROWS, 128>>>(z1, z2);
    k_simgemm<<<528, 256>>>();
    k_rowterm<<<NROWS / 4, 128>>>();
    k_final<<<1, 1>>>(out);
}